// round 2
// baseline (speedup 1.0000x reference)
#include <cuda_runtime.h>
#include <cstdint>

#define MDIM 256
#define LDIM 128
#define VPAD 260   // 260 % 32 == 4 -> conflict-free b-fragment LDS pattern

// ---------- helpers ----------

__device__ __forceinline__ unsigned f2tf32(float x) {
    unsigned r;
    asm("cvt.rna.tf32.f32 %0, %1;" : "=r"(r) : "f"(x));
    return r;
}

__device__ __forceinline__ void mma8(float* c, const unsigned* a, unsigned b0, unsigned b1) {
    asm volatile(
        "mma.sync.aligned.m16n8k8.row.col.f32.tf32.tf32.f32 "
        "{%0,%1,%2,%3}, {%4,%5,%6,%7}, {%8,%9}, {%0,%1,%2,%3};"
        : "+f"(c[0]), "+f"(c[1]), "+f"(c[2]), "+f"(c[3])
        : "r"(a[0]), "r"(a[1]), "r"(a[2]), "r"(a[3]), "r"(b0), "r"(b1));
}

// FMA/ALU-only tanh (no MUFU): tanh(|x|) = 1 - 2t/(1+t), t = e^{-2|x|}.
// exp2 via magic-constant round + degree-6 poly; reciprocal via bit-magic + 3 Newton.
// Max abs error ~1e-6.
__device__ __forceinline__ float fast_tanh(float x) {
    float ax = fabsf(x);
    float y  = fmaxf(ax * -2.8853900817779268f, -80.0f);   // -2*log2(e)*|x|
    float fk = y + 12582912.0f;                            // round to nearest int
    float f  = y - (fk - 12582912.0f);                     // frac in [-0.5, 0.5]
    int   k  = __float_as_int(fk) - 0x4B400000;            // integer part (<= 0)
    float scale = __int_as_float((k + 127) << 23);         // 2^k
    float p =            1.5403530393e-4f;                 // 2^f Taylor (ln2 powers)
    p = fmaf(p, f, 1.3333558146e-3f);
    p = fmaf(p, f, 9.6181291076e-3f);
    p = fmaf(p, f, 5.5504108665e-2f);
    p = fmaf(p, f, 2.4022650696e-1f);
    p = fmaf(p, f, 6.9314718056e-1f);
    p = fmaf(p, f, 1.0f);
    float t = p * scale;                                   // e^{-2|x|} in (0,1]
    float d = 1.0f + t;
    float r = __int_as_float(0x7EF127EAu - __float_as_uint(d));
    r = r * fmaf(-d, r, 2.0f);
    r = r * fmaf(-d, r, 2.0f);
    r = r * fmaf(-d, r, 2.0f);
    float th = fmaf(-(t + t), r, 1.0f);                    // 1 - 2 t r
    return __int_as_float(__float_as_int(th) | (__float_as_int(x) & 0x80000000));
}

// ---------- kernel ----------
// Grid: 1024 CTAs x 256 threads. Each CTA: 128 (b,t) rows for BOTH streams.
// Warps 0-3: h_1 rows (32 rows each); warps 4-7: h_2 same rows.
// Warp tile: 32 rows x 128 L-cols, K=256 in 32 steps of k8.
// v_tp kept tf32-converted in padded smem; b-fragments reused across 2 row blocks.

extern __shared__ unsigned smem_u[];

__global__ void __launch_bounds__(256, 1)
topo_attn_kernel(const float* __restrict__ h1, const float* __restrict__ h2,
                 const float* __restrict__ w,  const float* __restrict__ v,
                 float* __restrict__ out)
{
    unsigned* v_s = smem_u;                               // LDIM * VPAD tf32 words
    float*    w_s = (float*)(smem_u + LDIM * VPAD);       // 128 floats
    float*    s_s = w_s + LDIM;                           // 2 x 128 scores

    const int tid = threadIdx.x;

    // Stage v_tp (tf32-converted) and w_tp into smem.
    for (int i = tid; i < LDIM * MDIM; i += 256) {
        int l = i >> 8, m = i & 255;
        v_s[l * VPAD + m] = f2tf32(v[i]);
    }
    if (tid < LDIM) w_s[tid] = w[tid];
    __syncthreads();

    const int warp = tid >> 5, lane = tid & 31;
    const int g = lane >> 2, q = lane & 3;                // groupID / quad
    const int stream = warp >> 2;                         // 0 -> h1, 1 -> h2
    const float* h = stream ? h2 : h1;
    const long row0 = (long)blockIdx.x * 128 + (warp & 3) * 32;

    // Per-thread row pointers for the 4 fragment rows this thread owns.
    const float* pa[4];
#pragma unroll
    for (int j = 0; j < 4; j++) {
        int rb = j >> 1, hi = j & 1;
        pa[j] = h + (row0 + rb * 16 + hi * 8 + g) * MDIM + q;
    }

    float acc[2][16][4];
#pragma unroll
    for (int rb = 0; rb < 2; rb++)
#pragma unroll
        for (int nt = 0; nt < 16; nt++)
#pragma unroll
            for (int j = 0; j < 4; j++) acc[rb][nt][j] = 0.0f;

    // Software-pipelined K loop: prefetch next a-fragments during current MMAs.
    unsigned a_cur[2][4], a_nxt[2][4];
#pragma unroll
    for (int rb = 0; rb < 2; rb++) {
        a_cur[rb][0] = f2tf32(pa[rb * 2 + 0][0]);
        a_cur[rb][1] = f2tf32(pa[rb * 2 + 1][0]);
        a_cur[rb][2] = f2tf32(pa[rb * 2 + 0][4]);
        a_cur[rb][3] = f2tf32(pa[rb * 2 + 1][4]);
    }

#pragma unroll 2
    for (int ks = 0; ks < 32; ks++) {
        const int kn = (ks < 31 ? ks + 1 : 31) * 8;       // safe redundant last prefetch
#pragma unroll
        for (int rb = 0; rb < 2; rb++) {
            a_nxt[rb][0] = f2tf32(pa[rb * 2 + 0][kn]);
            a_nxt[rb][1] = f2tf32(pa[rb * 2 + 1][kn]);
            a_nxt[rb][2] = f2tf32(pa[rb * 2 + 0][kn + 4]);
            a_nxt[rb][3] = f2tf32(pa[rb * 2 + 1][kn + 4]);
        }
        const int k0 = ks * 8;
#pragma unroll
        for (int nt = 0; nt < 16; nt++) {
            unsigned b0 = v_s[(nt * 8 + g) * VPAD + k0 + q];
            unsigned b1 = v_s[(nt * 8 + g) * VPAD + k0 + q + 4];
            mma8(acc[0][nt], a_cur[0], b0, b1);
            mma8(acc[1][nt], a_cur[1], b0, b1);
        }
#pragma unroll
        for (int rb = 0; rb < 2; rb++)
#pragma unroll
            for (int j = 0; j < 4; j++) a_cur[rb][j] = a_nxt[rb][j];
    }

    // Epilogue: tanh -> weighted sum over 128 cols per row.
    float psum[4] = {0.f, 0.f, 0.f, 0.f};
#pragma unroll
    for (int rb = 0; rb < 2; rb++) {
#pragma unroll
        for (int nt = 0; nt < 16; nt++) {
            float w0 = w_s[nt * 8 + 2 * q];
            float w1 = w_s[nt * 8 + 2 * q + 1];
            psum[rb * 2 + 0] = fmaf(w0, fast_tanh(acc[rb][nt][0]), psum[rb * 2 + 0]);
            psum[rb * 2 + 0] = fmaf(w1, fast_tanh(acc[rb][nt][1]), psum[rb * 2 + 0]);
            psum[rb * 2 + 1] = fmaf(w0, fast_tanh(acc[rb][nt][2]), psum[rb * 2 + 1]);
            psum[rb * 2 + 1] = fmaf(w1, fast_tanh(acc[rb][nt][3]), psum[rb * 2 + 1]);
        }
    }
#pragma unroll
    for (int j = 0; j < 4; j++) {
        psum[j] += __shfl_xor_sync(0xFFFFFFFFu, psum[j], 1);
        psum[j] += __shfl_xor_sync(0xFFFFFFFFu, psum[j], 2);
    }
    if (q == 0) {
#pragma unroll
        for (int j = 0; j < 4; j++) {
            int row_local = (warp & 3) * 32 + (j >> 1) * 16 + (j & 1) * 8 + g;
            s_s[stream * 128 + row_local] = psum[j];
        }
    }
    __syncthreads();

    // 2-way softmax + transposed store: out[b][c][t].
    if (tid < 128) {
        float s0 = s_s[tid];
        float s1 = s_s[128 + tid];
        float dlt = s0 - s1;
        float a0 = 1.0f / (1.0f + expf(-dlt));
        long r = (long)blockIdx.x * 128 + tid;
        long b = r >> 12;           // T = 4096
        long t = r & 4095;
        out[b * 8192 + t]        = a0;
        out[b * 8192 + 4096 + t] = 1.0f - a0;
    }
}

// ---------- launch ----------

extern "C" void kernel_launch(void* const* d_in, const int* in_sizes, int n_in,
                              void* d_out, int out_size)
{
    const float* h1 = (const float*)d_in[0];
    const float* h2 = (const float*)d_in[1];
    const float* w  = (const float*)d_in[2];
    const float* v  = (const float*)d_in[3];
    // Defensive: identify w (128) vs v (32768) by element count.
    if (n_in >= 4 && in_sizes[2] > in_sizes[3]) { const float* tmp = w; w = v; v = tmp; }

    const int rows = in_sizes[0] / MDIM;   // B*T = 131072
    const int grid = rows / 128;           // 1024 CTAs
    const size_t smem = (size_t)(LDIM * VPAD) * 4 + LDIM * 4 + 256 * 4;  // ~134.7 KB

    cudaFuncSetAttribute(topo_attn_kernel,
                         cudaFuncAttributeMaxDynamicSharedMemorySize, (int)smem);
    topo_attn_kernel<<<grid, 256, smem>>>(h1, h2, w, v, (float*)d_out);
}

// round 3
// speedup vs baseline: 1.0894x; 1.0894x over previous
#include <cuda_runtime.h>
#include <cstdint>

#define MDIM   256
#define LDIM   128
#define VS     272          // v_s row stride in words; 272 % 32 == 16 -> conflict-free LDS.128
#define TDIM   4096
#define NBLK   2048         // 131072 rows / 64 rows per block
#define ROWS_TOTAL 131072

__device__ float g_scratch[NBLK * 2 * 64 * 4];   // [blk][stream][row64][Lq] partial scores (4MB)

// ---------- helpers ----------

__device__ __forceinline__ unsigned f2tf32(float x) {
    unsigned r;
    asm("cvt.rna.tf32.f32 %0, %1;" : "=r"(r) : "f"(x));
    return r;
}

__device__ __forceinline__ void mma8(float* c, const unsigned* a, unsigned b0, unsigned b1) {
    asm volatile(
        "mma.sync.aligned.m16n8k8.row.col.f32.tf32.tf32.f32 "
        "{%0,%1,%2,%3}, {%4,%5,%6,%7}, {%8,%9}, {%0,%1,%2,%3};"
        : "+f"(c[0]), "+f"(c[1]), "+f"(c[2]), "+f"(c[3])
        : "r"(a[0]), "r"(a[1]), "r"(a[2]), "r"(a[3]), "r"(b0), "r"(b1));
}

// tanh via MUFU: t = e^{-2|x|} (EX2), tanh = (1-t)/(1+t) (RCP), restore sign.
__device__ __forceinline__ float tanh_mufu(float x) {
    float ax = fabsf(x);
    float t, r;
    asm("ex2.approx.ftz.f32 %0, %1;" : "=f"(t) : "f"(ax * -2.885390081777927f));
    float u = 1.0f + t;
    asm("rcp.approx.ftz.f32 %0, %1;" : "=f"(r) : "f"(u));
    float th = (1.0f - t) * r;
    return __int_as_float(__float_as_int(th) | (__float_as_int(x) & 0x80000000));
}

// Load one k16 stage: 8 float4 (4 rb x {row g, row g+8}), contiguous 16B per row.
__device__ __forceinline__ void load_stage(float4* d, const float* base, int s) {
#pragma unroll
    for (int rb = 0; rb < 4; rb++) {
        d[2 * rb]     = *reinterpret_cast<const float4*>(base + rb * 4096 + s * 16);
        d[2 * rb + 1] = *reinterpret_cast<const float4*>(base + rb * 4096 + 2048 + s * 16);
    }
}

// ---------- kernel 1: GEMM + tanh + weighted partial reduction ----------
// Persistent: grid = #SMs, 256 threads (8 warps). Warp = 64 rows x 32 L-cols of one stream.
// Warps: stream = warp>>2, Lq = warp&3. Block = 64 rows of both streams.
// K handled as 16 "double-steps" (k16). Logical mma k-slots permuted so thread q's
// a-fragment for 2 ksteps = one LDG.128 and b-fragment = one LDS.128 (same permutation
// on both sides -> exact contraction).

extern __shared__ unsigned smem_u[];

__global__ void __launch_bounds__(256, 1)
topo_main_kernel(const float* __restrict__ h1, const float* __restrict__ h2,
                 const float* __restrict__ w,  const float* __restrict__ v,
                 int nblk)
{
    unsigned* v_s = smem_u;                             // LDIM x VS tf32 words
    float*    w_s = (float*)(smem_u + LDIM * VS);       // 128 floats

    const int tid = threadIdx.x;

    // One-time staging of v (tf32) and w.
    for (int i = tid; i < LDIM * MDIM; i += 256) {
        int l = i >> 8, m = i & 255;
        v_s[l * VS + m] = f2tf32(v[i]);
    }
    if (tid < LDIM) w_s[tid] = w[tid];
    __syncthreads();

    const int warp = tid >> 5, lane = tid & 31;
    const int g = lane >> 2, q = lane & 3;
    const int stream = warp >> 2, Lq = warp & 3;
    const float* hs = stream ? h2 : h1;
    const int l_base = Lq * 32;

    for (int blk = blockIdx.x; blk < nblk; blk += gridDim.x) {
        const float* base = hs + ((long)blk * 64 + g) * MDIM + 4 * q;

        float acc[4][4][4];
#pragma unroll
        for (int rb = 0; rb < 4; rb++)
#pragma unroll
            for (int nt = 0; nt < 4; nt++)
#pragma unroll
                for (int j = 0; j < 4; j++) acc[rb][nt][j] = 0.0f;

        float4 buf[3][8];
#pragma unroll
        for (int p = 0; p < 3; p++) load_stage(buf[p], base, p);

#pragma unroll
        for (int s = 0; s < 16; s++) {
            float4 cur[8];
#pragma unroll
            for (int i = 0; i < 8; i++) cur[i] = buf[s % 3][i];
            if (s + 3 < 16) load_stage(buf[s % 3], base, s + 3);

            // Convert current stage to tf32 fragments (ksteps A and B).
            unsigned aA[4][4], aB[4][4];
#pragma unroll
            for (int rb = 0; rb < 4; rb++) {
                aA[rb][0] = f2tf32(cur[2 * rb].x);     // row g,   slot q
                aA[rb][1] = f2tf32(cur[2 * rb + 1].x); // row g+8, slot q
                aA[rb][2] = f2tf32(cur[2 * rb].y);     // row g,   slot q+4
                aA[rb][3] = f2tf32(cur[2 * rb + 1].y);
                aB[rb][0] = f2tf32(cur[2 * rb].z);
                aB[rb][1] = f2tf32(cur[2 * rb + 1].z);
                aB[rb][2] = f2tf32(cur[2 * rb].w);
                aB[rb][3] = f2tf32(cur[2 * rb + 1].w);
            }
#pragma unroll
            for (int nt = 0; nt < 4; nt++) {
                // b for both ksteps in one LDS.128 (16B-aligned, conflict-free).
                const uint4 b = *reinterpret_cast<const uint4*>(
                    v_s + (l_base + nt * 8 + g) * VS + 16 * s + 4 * q);
#pragma unroll
                for (int rb = 0; rb < 4; rb++) {
                    mma8(acc[rb][nt], aA[rb], b.x, b.y);
                    mma8(acc[rb][nt], aB[rb], b.z, b.w);
                }
            }
        }

        // Epilogue: tanh, weight by w, sum over this warp's 32 L columns.
        float psum[8];
#pragma unroll
        for (int j = 0; j < 8; j++) psum[j] = 0.0f;
#pragma unroll
        for (int rb = 0; rb < 4; rb++) {
#pragma unroll
            for (int nt = 0; nt < 4; nt++) {
                float w0 = w_s[l_base + nt * 8 + 2 * q];
                float w1 = w_s[l_base + nt * 8 + 2 * q + 1];
                psum[2 * rb]     = fmaf(w0, tanh_mufu(acc[rb][nt][0]), psum[2 * rb]);
                psum[2 * rb]     = fmaf(w1, tanh_mufu(acc[rb][nt][1]), psum[2 * rb]);
                psum[2 * rb + 1] = fmaf(w0, tanh_mufu(acc[rb][nt][2]), psum[2 * rb + 1]);
                psum[2 * rb + 1] = fmaf(w1, tanh_mufu(acc[rb][nt][3]), psum[2 * rb + 1]);
            }
        }
#pragma unroll
        for (int j = 0; j < 8; j++) {
            psum[j] += __shfl_xor_sync(0xFFFFFFFFu, psum[j], 1);
            psum[j] += __shfl_xor_sync(0xFFFFFFFFu, psum[j], 2);
        }
        if (q == 0) {
            float* sc = g_scratch + ((blk * 2 + stream) * 64) * 4 + Lq;
#pragma unroll
            for (int j = 0; j < 8; j++) {
                int row_local = (j >> 1) * 16 + (j & 1) * 8 + g;
                sc[row_local * 4] = psum[j];
            }
        }
    }
}

// ---------- kernel 2: combine partials + 2-way softmax + transposed store ----------

__global__ void __launch_bounds__(256)
topo_combine_kernel(float* __restrict__ out, int rows)
{
    int r = blockIdx.x * 256 + threadIdx.x;
    if (r >= rows) return;
    int blk = r >> 6, rl = r & 63;
    const float4 v0 = *reinterpret_cast<const float4*>(g_scratch + ((blk * 2 + 0) * 64 + rl) * 4);
    const float4 v1 = *reinterpret_cast<const float4*>(g_scratch + ((blk * 2 + 1) * 64 + rl) * 4);
    float s0 = (v0.x + v0.y) + (v0.z + v0.w);
    float s1 = (v1.x + v1.y) + (v1.z + v1.w);
    float e;
    asm("ex2.approx.ftz.f32 %0, %1;" : "=f"(e) : "f"((s1 - s0) * 1.4426950408889634f));
    float rcp;
    float d = 1.0f + e;
    asm("rcp.approx.ftz.f32 %0, %1;" : "=f"(rcp) : "f"(d));
    float a0 = rcp;                  // sigmoid(s0 - s1)
    int b = r >> 12, t = r & (TDIM - 1);
    out[(long)b * 2 * TDIM + t]        = a0;
    out[(long)b * 2 * TDIM + TDIM + t] = 1.0f - a0;
}

// ---------- launch ----------

extern "C" void kernel_launch(void* const* d_in, const int* in_sizes, int n_in,
                              void* d_out, int out_size)
{
    const float* h1 = (const float*)d_in[0];
    const float* h2 = (const float*)d_in[1];
    const float* w  = (const float*)d_in[2];
    const float* v  = (const float*)d_in[3];
    if (n_in >= 4 && in_sizes[2] > in_sizes[3]) { const float* tmp = w; w = v; v = tmp; }

    const int rows = in_sizes[0] / MDIM;     // 131072
    const int nblk = rows / 64;              // 2048

    int nsm = 148;
    cudaDeviceGetAttribute(&nsm, cudaDevAttrMultiProcessorCount, 0);

    const size_t smem = (size_t)(LDIM * VS) * 4 + LDIM * 4;   // ~139.8 KB
    cudaFuncSetAttribute(topo_main_kernel,
                         cudaFuncAttributeMaxDynamicSharedMemorySize, (int)smem);

    topo_main_kernel<<<nsm, 256, smem>>>(h1, h2, w, v, nblk);
    topo_combine_kernel<<<(rows + 255) / 256, 256>>>((float*)d_out, rows);
}

// round 6
// speedup vs baseline: 1.6747x; 1.5372x over previous
#include <cuda_runtime.h>
#include <cstdint>

#define V_OFF   0
#define VS      272                      // v row stride in words (16-bank skew)
#define H_OFF   139264                   // 128*272*4
#define H_STG   32768                    // one stage: 256 rows x 32 floats
#define W_OFF   204800                   // H_OFF + 2*H_STG
#define S_OFF   205312
#define SMEM_SZ 209408

__device__ __forceinline__ uint32_t smem_u32(const void* p) {
    uint32_t a;
    asm("{ .reg .u64 t; cvta.to.shared.u64 t, %1; cvt.u32.u64 %0, t; }" : "=r"(a) : "l"(p));
    return a;
}

__device__ __forceinline__ void mma8(float* c, unsigned a0, unsigned a1, unsigned a2,
                                     unsigned a3, unsigned b0, unsigned b1) {
    asm volatile(
        "mma.sync.aligned.m16n8k8.row.col.f32.tf32.tf32.f32 "
        "{%0,%1,%2,%3}, {%4,%5,%6,%7}, {%8,%9}, {%0,%1,%2,%3};"
        : "+f"(c[0]), "+f"(c[1]), "+f"(c[2]), "+f"(c[3])
        : "r"(a0), "r"(a1), "r"(a2), "r"(a3), "r"(b0), "r"(b1));
}

__device__ __forceinline__ float tanh_mufu(float x) {
    float ax = fabsf(x);
    float t, r;
    asm("ex2.approx.ftz.f32 %0, %1;" : "=f"(t) : "f"(ax * -2.885390081777927f));
    asm("rcp.approx.ftz.f32 %0, %1;" : "=f"(r) : "f"(1.0f + t));
    float th = (1.0f - t) * r;
    return __int_as_float(__float_as_int(th) | (__float_as_int(x) & 0x80000000));
}

// ---------------- kernel ----------------
// 512 threads, persistent. Warp: 64 rows x 32 L of one stream; tile = 128 (b,t)
// rows x 2 streams. h staged fp32 via cp.async (k32 chunks, double buffer,
// parity swizzle); A fed to tf32 mma as raw fp32 bits (HW truncation).

extern "C" __global__ void __launch_bounds__(512, 1)
topo_mma_kernel(const float* __restrict__ h1, const float* __restrict__ h2,
                const float* __restrict__ w,  const float* __restrict__ v,
                float* __restrict__ out, int ntiles)
{
    extern __shared__ char sm[];
    const uint32_t sb = smem_u32(sm);
    const int tid = threadIdx.x;

    // One-time staging: v (rna->tf32, padded) and w.
    for (int i = tid; i < 128 * 256; i += 512) {
        int l = i >> 8, m = i & 255;
        unsigned tv;
        asm("cvt.rna.tf32.f32 %0, %1;" : "=r"(tv) : "f"(v[i]));
        *(unsigned*)(sm + (l * VS + m) * 4) = tv;
    }
    if (tid < 128) ((float*)(sm + W_OFF))[tid] = w[tid];
    __syncthreads();

    const int lane = tid & 31, wid = tid >> 5;
    const int g = lane >> 2, q = lane & 3;
    const int stream = wid >> 3, rg = (wid >> 2) & 1, Lq = wid & 3;
    const int ru_base = stream * 128 + rg * 64;
    const int l_base = Lq * 32;

    // Producer constants.
    const int t8 = tid >> 3, og = tid & 7;
    const uint32_t pswz = (uint32_t)((og ^ ((t8 & 1) << 2)) << 4);
    const float* hsel[2] = {h1, h2};

    // w pairs for this warp's columns (constant across tiles).
    float2 wv[4];
#pragma unroll
    for (int nt = 0; nt < 4; nt++) {
        wv[nt].x = ((const float*)(sm + W_OFF))[l_base + nt * 8 + 2 * q];
        wv[nt].y = ((const float*)(sm + W_OFF))[l_base + nt * 8 + 2 * q + 1];
    }

    // Per-lane swizzled group offsets for a-loads (parity of row == parity of g).
    const uint32_t sw0 = (uint32_t)(((q)     ^ ((g & 1) << 2)) << 4);   // d=0
    const uint32_t sw1 = (uint32_t)(((4 + q) ^ ((g & 1) << 2)) << 4);   // d=1

    // b row base word offsets.
    uint32_t vrow[4];
#pragma unroll
    for (int nt = 0; nt < 4; nt++)
        vrow[nt] = (uint32_t)((l_base + nt * 8 + g) * VS + q * 4);

#define ISSUE(tile_, c_, buf_) do {                                           \
    _Pragma("unroll")                                                         \
    for (int j = 0; j < 4; j++) {                                             \
        int ru = j * 64 + t8;                                                 \
        int st = ru >> 7, r = ru & 127;                                       \
        const float* src = hsel[st] + ((long)((tile_) * 128 + r)) * 256       \
                         + (c_) * 32 + og * 4;                                \
        uint32_t dst = sb + H_OFF + (buf_) * H_STG + (uint32_t)ru * 128 + pswz; \
        asm volatile("cp.async.cg.shared.global [%0], [%1], 16;"              \
                     :: "r"(dst), "l"(src) : "memory");                       \
    }                                                                         \
    asm volatile("cp.async.commit_group;" ::: "memory");                      \
} while (0)

    int tile = blockIdx.x;
    if (tile < ntiles) { ISSUE(tile, 0, 0); ISSUE(tile, 1, 1); }

    for (; tile < ntiles; tile += gridDim.x) {
        float acc[4][4][4];
#pragma unroll
        for (int rb = 0; rb < 4; rb++)
#pragma unroll
            for (int nt = 0; nt < 4; nt++)
#pragma unroll
                for (int j = 0; j < 4; j++) acc[rb][nt][j] = 0.0f;

#pragma unroll 1
        for (int c = 0; c < 8; c++) {
            if (c == 7) asm volatile("cp.async.wait_group 0;" ::: "memory");
            else        asm volatile("cp.async.wait_group 1;" ::: "memory");
            __syncthreads();

            const char* hb = sm + H_OFF + ((c & 1) << 15);
            const char* vb = sm + (uint32_t)(c * 32) * 4;
#pragma unroll
            for (int d = 0; d < 2; d++) {
                const uint32_t sw = d ? sw1 : sw0;
                uint4 va[4][2];
#pragma unroll
                for (int rb = 0; rb < 4; rb++) {
                    const int ru = ru_base + rb * 16 + g;
                    va[rb][0] = *(const uint4*)(hb + (uint32_t)ru * 128 + sw);
                    va[rb][1] = *(const uint4*)(hb + (uint32_t)(ru + 8) * 128 + sw);
                }
#pragma unroll
                for (int nt = 0; nt < 4; nt++) {
                    const uint4 b = *(const uint4*)(vb + (vrow[nt] + d * 16) * 4);
#pragma unroll
                    for (int rb = 0; rb < 4; rb++) {
                        mma8(acc[rb][nt], va[rb][0].x, va[rb][1].x,
                             va[rb][0].y, va[rb][1].y, b.x, b.y);
                        mma8(acc[rb][nt], va[rb][0].z, va[rb][1].z,
                             va[rb][0].w, va[rb][1].w, b.z, b.w);
                    }
                }
            }
            __syncthreads();

            if (c < 6) {
                ISSUE(tile, c + 2, c & 1);
            } else if (c == 7) {
                int tn = tile + gridDim.x;
                if (tn < ntiles) { ISSUE(tn, 0, 0); ISSUE(tn, 1, 1); }
            }
        }

        // Epilogue: tanh + w-dot, reduce over q, stash partials.
        float psum[8];
#pragma unroll
        for (int j = 0; j < 8; j++) psum[j] = 0.0f;
#pragma unroll
        for (int rb = 0; rb < 4; rb++)
#pragma unroll
            for (int nt = 0; nt < 4; nt++) {
                psum[2*rb]   = fmaf(wv[nt].x, tanh_mufu(acc[rb][nt][0]), psum[2*rb]);
                psum[2*rb]   = fmaf(wv[nt].y, tanh_mufu(acc[rb][nt][1]), psum[2*rb]);
                psum[2*rb+1] = fmaf(wv[nt].x, tanh_mufu(acc[rb][nt][2]), psum[2*rb+1]);
                psum[2*rb+1] = fmaf(wv[nt].y, tanh_mufu(acc[rb][nt][3]), psum[2*rb+1]);
            }
#pragma unroll
        for (int j = 0; j < 8; j++) {
            psum[j] += __shfl_xor_sync(0xFFFFFFFFu, psum[j], 1);
            psum[j] += __shfl_xor_sync(0xFFFFFFFFu, psum[j], 2);
        }
        if (q == 0) {
            float* ss = (float*)(sm + S_OFF);
#pragma unroll
            for (int j = 0; j < 8; j++) {
                int row = rg * 64 + (j >> 1) * 16 + (j & 1) * 8 + g;
                ss[(stream * 128 + row) * 4 + Lq] = psum[j];
            }
        }
        __syncthreads();

        // 2-way softmax + transposed store.
        if (tid < 128) {
            const float4* s4 = (const float4*)(sm + S_OFF);
            float4 p0 = s4[tid];
            float4 p1 = s4[128 + tid];
            float s0 = (p0.x + p0.y) + (p0.z + p0.w);
            float s1 = (p1.x + p1.y) + (p1.z + p1.w);
            float e, rc;
            asm("ex2.approx.ftz.f32 %0, %1;" : "=f"(e)
                : "f"((s1 - s0) * 1.4426950408889634f));
            asm("rcp.approx.ftz.f32 %0, %1;" : "=f"(rc) : "f"(1.0f + e));
            int row = tile * 128 + tid;
            int b = row >> 12, t = row & 4095;
            out[(long)b * 8192 + t]        = rc;
            out[(long)b * 8192 + 4096 + t] = e * rc;
        }
        // s_s safe: next writes occur only after next tile's chunk barriers.
    }
#undef ISSUE
}

// ---------------- launch ----------------

extern "C" void kernel_launch(void* const* d_in, const int* in_sizes, int n_in,
                              void* d_out, int out_size)
{
    const float* h1 = (const float*)d_in[0];
    const float* h2 = (const float*)d_in[1];
    const float* w  = (const float*)d_in[2];
    const float* v  = (const float*)d_in[3];
    if (n_in >= 4 && in_sizes[2] > in_sizes[3]) { const float* tmp = w; w = v; v = tmp; }

    const int rows   = in_sizes[0] / 256;    // 131072
    const int ntiles = rows / 128;           // 1024

    int nsm = 148;
    cudaDeviceGetAttribute(&nsm, cudaDevAttrMultiProcessorCount, 0);
    int grid = nsm < ntiles ? nsm : ntiles;

    cudaFuncSetAttribute(topo_mma_kernel,
                         cudaFuncAttributeMaxDynamicSharedMemorySize, SMEM_SZ);
    topo_mma_kernel<<<grid, 512, SMEM_SZ>>>(h1, h2, w, v, (float*)d_out, ntiles);
}